// round 7
// baseline (speedup 1.0000x reference)
#include <cuda_runtime.h>
#include <cstdint>

// Decoder_90486370992920
// Inputs: d_in[0] partition [N,64] f32, d_in[1] abs_actions [64] f32,
//         d_in[2] u [N,64] f32, d_in[3] W [N,2,2] f32, d_in[4] b [N,2] f32
// Output: weights [N,2] f32 at [0,2N), actions [N,2] at [2N,4N)
//
// Key (R6, proven): m' = d*(1-p)*rcp(p), d = log2(u) < 0; rcp = raw approx +
// one Newton step; no cancellation anywhere -> noise class gives a stable
// single argmax flip (rel_err 6.17e-4). argmax r/s == argmax m' (FMAX).
// R7 layout: 4 lanes/agent x 16 elems/lane, two-phase (8+8) per-lane
// recovery so only (km, idx) persists per half; __ldcs streaming loads.
// Ties: lower index wins everywhere (phase A preferred on ==, descending
// eq-chain, lowest lane via ballot+ffs) == reference first-occurrence rule.
// weights = 1/(1+exp(-y)) accurate expf, subnormal flushed to 0 (XLA FTZ).
// actions = (w>0).

static constexpr int M = 64;
static constexpr int LPA = 4;            // lanes per agent
static constexpr int EPL = 16;           // elements per lane
static constexpr int THREADS = 256;
static constexpr int AGENTS_PER_BLOCK = THREADS / LPA;   // 64

__device__ __forceinline__ float key_m(float p, float uu)
{
    float q = 1.0f - p;                                 // exact for p>=0.5, <=1/2 ulp else
    float t;
    asm("rcp.approx.f32 %0, %1;" : "=f"(t) : "f"(p));   // ~1/p, raw approx
    t = t * __fmaf_rn(-p, t, 2.0f);                     // Newton -> ~0.5 ulp
    float d = __log2f(uu);                              // MUFU.LG2, d < 0
    return (d * q) * t;                                 // m' = d*(1-p)/p < 0
}

// process 8 elements (two float4 pairs); returns km and writes idx (0..7 local)
__device__ __forceinline__ void block8(const float4& pa, const float4& pb,
                                       const float4& ua, const float4& ub,
                                       float& km, int& idx)
{
    float m0 = key_m(pa.x, ua.x);
    float m1 = key_m(pa.y, ua.y);
    float m2 = key_m(pa.z, ua.z);
    float m3 = key_m(pa.w, ua.w);
    float m4 = key_m(pb.x, ub.x);
    float m5 = key_m(pb.y, ub.y);
    float m6 = key_m(pb.z, ub.z);
    float m7 = key_m(pb.w, ub.w);

    float a = fmaxf(fmaxf(m0, m1), fmaxf(m2, m3));
    float c = fmaxf(fmaxf(m4, m5), fmaxf(m6, m7));
    km = fmaxf(a, c);

    int li = 0;
    if (m7 == km) li = 7;
    if (m6 == km) li = 6;
    if (m5 == km) li = 5;
    if (m4 == km) li = 4;
    if (m3 == km) li = 3;
    if (m2 == km) li = 2;
    if (m1 == km) li = 1;
    if (m0 == km) li = 0;
    idx = li;
}

__global__ __launch_bounds__(THREADS)
void decoder_kernel(const float* __restrict__ part,
                    const float* __restrict__ absa,
                    const float* __restrict__ u,
                    const float* __restrict__ W,
                    const float* __restrict__ b,
                    float* __restrict__ out,
                    int nAgents,
                    long long outSize)
{
    __shared__ float sabs[M];
    if (threadIdx.x < M) sabs[threadIdx.x] = absa[threadIdx.x];
    __syncthreads();

    const int lane = threadIdx.x & 31;
    const int sub  = lane & (LPA - 1);          // 0..3 within agent
    const int grp  = lane >> 2;                 // agent slot within warp (0..7)
    const int gwarp = (int)((blockIdx.x * (unsigned)blockDim.x + threadIdx.x) >> 5);
    const int agent = gwarp * 8 + grp;

    const int ag = agent < nAgents ? agent : (nAgents - 1);
    const size_t rowBase = (size_t)ag * M + sub * EPL;

    // front-batch all 8 streaming loads (MLP, evict-first)
    const float4 pA0 = __ldcs(reinterpret_cast<const float4*>(part + rowBase));
    const float4 pA1 = __ldcs(reinterpret_cast<const float4*>(part + rowBase + 4));
    const float4 pB0 = __ldcs(reinterpret_cast<const float4*>(part + rowBase + 8));
    const float4 pB1 = __ldcs(reinterpret_cast<const float4*>(part + rowBase + 12));
    const float4 uA0 = __ldcs(reinterpret_cast<const float4*>(u + rowBase));
    const float4 uA1 = __ldcs(reinterpret_cast<const float4*>(u + rowBase + 4));
    const float4 uB0 = __ldcs(reinterpret_cast<const float4*>(u + rowBase + 8));
    const float4 uB1 = __ldcs(reinterpret_cast<const float4*>(u + rowBase + 12));

    float kmA, kmB; int iA, iB;
    block8(pA0, pA1, uA0, uA1, kmA, iA);
    block8(pB0, pB1, uB0, uB1, kmB, iB);

    // merge halves: tie keeps A (lower index)
    float km = kmA;
    int   li = iA;                       // local 0..7
    if (kmB > kmA) { km = kmB; li = iB + 8; }
    li += sub * EPL;                     // 0..63

    // cross-lane max over the 4 lanes of this agent
    float klane = km;
    #pragma unroll
    for (int off = 2; off > 0; off >>= 1)
        km = fmaxf(km, __shfl_xor_sync(0xffffffffu, km, off, LPA));

    // lowest hitting lane (lanes ordered by ascending index range)
    unsigned bal = __ballot_sync(0xffffffffu, klane == km);
    unsigned gmask = (bal >> (grp * LPA)) & 0xFu;
    int leader = __ffs((int)gmask) - 1;
    int widx = __shfl_sync(0xffffffffu, li, grp * LPA + leader);

    if (sub == 0 && agent < nAgents) {
        const float x0 = (float)widx;
        const float x1 = sabs[widx];

        const float4 w  = __ldcs(reinterpret_cast<const float4*>(W + (size_t)agent * 4));
        const float2 bb = __ldcs(reinterpret_cast<const float2*>(b + (size_t)agent * 2));

        float y0 = fmaf(w.x, x0, fmaf(w.y, x1, bb.x));
        float y1 = fmaf(w.z, x0, fmaf(w.w, x1, bb.y));

        // naive sigmoid, accurate expf, FTZ flush of subnormal results
        float s0 = 1.0f / (1.0f + expf(-y0));
        float s1 = 1.0f / (1.0f + expf(-y1));
        if (s0 < 1.17549435e-38f) s0 = 0.0f;
        if (s1 < 1.17549435e-38f) s1 = 0.0f;

        reinterpret_cast<float2*>(out + (size_t)agent * 2)[0] = make_float2(s0, s1);

        if (outSize >= 4LL * nAgents) {
            float a0 = (s0 > 0.0f) ? 1.0f : 0.0f;
            float a1 = (s1 > 0.0f) ? 1.0f : 0.0f;
            reinterpret_cast<float2*>(out + 2LL * nAgents + (size_t)agent * 2)[0] =
                make_float2(a0, a1);
        }
    }
}

extern "C" void kernel_launch(void* const* d_in, const int* in_sizes, int n_in,
                              void* d_out, int out_size)
{
    const float* part = (const float*)d_in[0];
    const float* absa = (const float*)d_in[1];
    const float* u    = (const float*)d_in[2];
    const float* W    = (const float*)d_in[3];
    const float* b    = (const float*)d_in[4];
    float* out = (float*)d_out;

    const int nAgents = in_sizes[0] / M;
    const int blocks = (nAgents + AGENTS_PER_BLOCK - 1) / AGENTS_PER_BLOCK;

    decoder_kernel<<<blocks, THREADS>>>(part, absa, u, W, b, out, nAgents,
                                        (long long)out_size);
}

// round 8
// speedup vs baseline: 1.0365x; 1.0365x over previous
#include <cuda_runtime.h>
#include <cstdint>

// Decoder_90486370992920
// Inputs: d_in[0] partition [N,64] f32, d_in[1] abs_actions [64] f32,
//         d_in[2] u [N,64] f32, d_in[3] W [N,2,2] f32, d_in[4] b [N,2] f32
// Output: weights [N,2] f32 at [0,2N), actions [N,2] at [2N,4N)
//
// Key (R6, proven): m' = d*(1-p)*rcp(p), d = log2(u) < 0; rcp = raw approx +
// one Newton step; no cancellation -> stable single argmax flip (6.17e-4).
// argmax r/s == argmax m' -> FMAX reduce; exact-equality + ballot recovery,
// lowest lane/slot first == reference first-occurrence tie rule.
// R8 deltas vs R6 (layout identical: 8 lanes/agent x 8 elems/lane, 256 thr):
//   - __ldcs/__stcs streaming on all single-touch traffic (evict-first)
//   - W/b epilogue loads hoisted ABOVE the reduction: their DRAM latency
//     overlaps the key math + shuffle tree instead of forming a dependent
//     per-warp tail.
// weights = 1/(1+exp(-y)) accurate expf, subnormal flushed to 0 (XLA FTZ,
// established R2->R3). actions = (w>0).

static constexpr int M = 64;
static constexpr int LPA = 8;            // lanes per agent
static constexpr int EPL = 8;            // elements per lane
static constexpr int THREADS = 256;
static constexpr int AGENTS_PER_BLOCK = THREADS / LPA;   // 32

__device__ __forceinline__ float key_m(float p, float uu)
{
    float q = 1.0f - p;                                 // exact for p>=0.5, <=1/2 ulp else
    float t;
    asm("rcp.approx.f32 %0, %1;" : "=f"(t) : "f"(p));   // ~1/p, raw approx
    t = t * __fmaf_rn(-p, t, 2.0f);                     // Newton -> ~0.5 ulp
    float d = __log2f(uu);                              // MUFU.LG2, d < 0
    return (d * q) * t;                                 // m' = d*(1-p)/p < 0
}

__global__ __launch_bounds__(THREADS)
void decoder_kernel(const float* __restrict__ part,
                    const float* __restrict__ absa,
                    const float* __restrict__ u,
                    const float* __restrict__ W,
                    const float* __restrict__ b,
                    float* __restrict__ out,
                    int nAgents,
                    long long outSize)
{
    __shared__ float sabs[M];
    if (threadIdx.x < M) sabs[threadIdx.x] = absa[threadIdx.x];
    __syncthreads();

    const int lane = threadIdx.x & 31;
    const int sub  = lane & (LPA - 1);          // 0..7 within agent
    const int grp  = lane >> 3;                 // agent slot within warp (0..3)
    const int gwarp = (int)((blockIdx.x * (unsigned)blockDim.x + threadIdx.x) >> 5);
    const int agent = gwarp * 4 + grp;

    const int ag = agent < nAgents ? agent : (nAgents - 1);
    const size_t rowBase = (size_t)ag * M + sub * EPL;

    // front-batched streaming loads (evict-first; zero reuse)
    const float4 p0 = __ldcs(reinterpret_cast<const float4*>(part + rowBase));
    const float4 p1 = __ldcs(reinterpret_cast<const float4*>(part + rowBase + 4));
    const float4 u0 = __ldcs(reinterpret_cast<const float4*>(u + rowBase));
    const float4 u1 = __ldcs(reinterpret_cast<const float4*>(u + rowBase + 4));

    // hoisted epilogue loads: latency overlaps key math + reduction below
    float4 w;  float2 bb;
    const bool writer = (sub == 0) && (agent < nAgents);
    if (writer) {
        w  = __ldcs(reinterpret_cast<const float4*>(W + (size_t)agent * 4));
        bb = __ldcs(reinterpret_cast<const float2*>(b + (size_t)agent * 2));
    }

    float m0 = key_m(p0.x, u0.x);
    float m1 = key_m(p0.y, u0.y);
    float m2 = key_m(p0.z, u0.z);
    float m3 = key_m(p0.w, u0.w);
    float m4 = key_m(p1.x, u1.x);
    float m5 = key_m(p1.y, u1.y);
    float m6 = key_m(p1.z, u1.z);
    float m7 = key_m(p1.w, u1.w);

    // within-lane max (== argmax of r/s)
    float a = fmaxf(fmaxf(m0, m1), fmaxf(m2, m3));
    float c = fmaxf(fmaxf(m4, m5), fmaxf(m6, m7));
    float km = fmaxf(a, c);

    // cross-lane max over the 8 lanes of this agent
    #pragma unroll
    for (int off = 4; off > 0; off >>= 1)
        km = fmaxf(km, __shfl_xor_sync(0xffffffffu, km, off, LPA));

    // index recovery: exact equality against km; lowest slot wins within lane
    const int base = sub * EPL;
    int li = 1 << 20;
    if (m7 == km) li = base + 7;
    if (m6 == km) li = base + 6;
    if (m5 == km) li = base + 5;
    if (m4 == km) li = base + 4;
    if (m3 == km) li = base + 3;
    if (m2 == km) li = base + 2;
    if (m1 == km) li = base + 1;
    if (m0 == km) li = base + 0;

    unsigned bal = __ballot_sync(0xffffffffu, li < (1 << 20));
    unsigned gmask = (bal >> (grp * LPA)) & 0xffu;    // hits within this agent's lanes
    int leader = __ffs((int)gmask) - 1;               // lowest lane -> lowest index
    int widx = __shfl_sync(0xffffffffu, li, grp * LPA + leader);

    if (writer) {
        const float x0 = (float)widx;
        const float x1 = sabs[widx];

        float y0 = fmaf(w.x, x0, fmaf(w.y, x1, bb.x));
        float y1 = fmaf(w.z, x0, fmaf(w.w, x1, bb.y));

        // naive sigmoid, accurate expf, FTZ flush of subnormal results
        float s0 = 1.0f / (1.0f + expf(-y0));
        float s1 = 1.0f / (1.0f + expf(-y1));
        if (s0 < 1.17549435e-38f) s0 = 0.0f;
        if (s1 < 1.17549435e-38f) s1 = 0.0f;

        __stcs(reinterpret_cast<float2*>(out + (size_t)agent * 2),
               make_float2(s0, s1));

        if (outSize >= 4LL * nAgents) {
            float a0 = (s0 > 0.0f) ? 1.0f : 0.0f;
            float a1 = (s1 > 0.0f) ? 1.0f : 0.0f;
            __stcs(reinterpret_cast<float2*>(out + 2LL * nAgents + (size_t)agent * 2),
                   make_float2(a0, a1));
        }
    }
}

extern "C" void kernel_launch(void* const* d_in, const int* in_sizes, int n_in,
                              void* d_out, int out_size)
{
    const float* part = (const float*)d_in[0];
    const float* absa = (const float*)d_in[1];
    const float* u    = (const float*)d_in[2];
    const float* W    = (const float*)d_in[3];
    const float* b    = (const float*)d_in[4];
    float* out = (float*)d_out;

    const int nAgents = in_sizes[0] / M;
    const int blocks = (nAgents + AGENTS_PER_BLOCK - 1) / AGENTS_PER_BLOCK;

    decoder_kernel<<<blocks, THREADS>>>(part, absa, u, W, b, out, nAgents,
                                        (long long)out_size);
}